// round 9
// baseline (speedup 1.0000x reference)
#include <cuda_runtime.h>
#include <cstdint>

#define OUT_HW   7
#define NBINS    49            // 7*7
#define CH       256
#define FH       256
#define FW       256
#define HWSZ     (FH*FW)       // 65536
#define CHWSZ    (CH*HWSZ)
#define BPB      16            // bins per block (8 warps x 2 bins)
#define CUNROLL  8             // channels in flight per warp

// Permutation: rois sorted by (batch, spatial tile) for L2 locality.
__device__ unsigned int g_perm[1024];

__global__ void sort_rois_kernel(const float* __restrict__ rois, int n)
{
    __shared__ unsigned int sk[1024];
    const int t = threadIdx.x;

    unsigned int key;
    if (t < n && n <= 1024) {
        const float* r = rois + t * 6;
        const int   b  = (int)__ldg(r + 0);
        const float cx = __ldg(r + 1) * 0.25f;   // feature-space center
        const float cy = __ldg(r + 2) * 0.25f;
        int tx = (int)(cx * (1.0f / 32.0f)); tx = min(max(tx, 0), 7);
        int ty = (int)(cy * (1.0f / 32.0f)); ty = min(max(ty, 0), 7);
        const unsigned int k = (unsigned int)(b * 64 + ty * 8 + tx);
        key = (k << 10) | (unsigned int)t;
    } else {
        key = 0xFFFFFFFFu;
    }
    sk[t] = key;
    __syncthreads();

    for (int k = 2; k <= 1024; k <<= 1) {
        for (int j = k >> 1; j > 0; j >>= 1) {
            const int ixj = t ^ j;
            if (ixj > t) {
                const unsigned int a = sk[t];
                const unsigned int c = sk[ixj];
                const bool up = ((t & k) == 0);
                if ((a > c) == up) { sk[t] = c; sk[ixj] = a; }
            }
            __syncthreads();
        }
    }

    if (t < n) {
        g_perm[t] = (n <= 1024) ? (sk[t] & 1023u) : (unsigned int)t;
    }
}

// Lane layout within a warp: lane = bpair*16 + sample*4 + corner.
// Each lane owns ONE gather address + ONE premultiplied weight, reused
// across all 256 channels. 4-step shfl.bfly reduces 16 lanes -> 1 bin value.
__global__ __launch_bounds__(256, 8)
void rroi_align_kernel(const float* __restrict__ feat,
                       const float* __restrict__ rois,
                       float* __restrict__ out)
{
    const int n    = (int)g_perm[blockIdx.y];   // sorted roi order
    const int warp = threadIdx.x >> 5;
    const int lane = threadIdx.x & 31;

    const int binpair = blockIdx.x * BPB + warp * 2;  // first bin of this warp's pair
    if (binpair >= NBINS) return;                     // warp-uniform exit

    const int bsel   = (lane >> 4) & 1;   // which bin of the pair
    const int s      = (lane >> 2) & 3;   // sample 0..3 (2x2)
    const int corner = lane & 3;          // 0..3 bilinear corner
    const int bin    = binpair + bsel;
    const bool active = (bin < NBINS);

    // ---- per-roi parameters (broadcast loads) ----
    const float* r = rois + n * 6;
    const int   b  = (int)__ldg(r + 0);
    const float cx = __ldg(r + 1) * 0.25f;
    const float cy = __ldg(r + 2) * 0.25f;
    const float rw = fmaxf(__ldg(r + 3) * 0.25f, 0.0f);
    const float rh = fmaxf(__ldg(r + 4) * 0.25f, 0.0f);
    const float th = __ldg(r + 5);

    const float cs = cosf(th);
    const float sn = sinf(th);
    const float bh = rh * (1.0f / OUT_HW);
    const float bw = rw * (1.0f / OUT_HW);

    const int ph = bin / OUT_HW;
    const int pw = bin - ph * OUT_HW;

    // ---- this lane's sample geometry ----
    const float sy = (s >> 1) ? 0.75f : 0.25f;
    const float sx = (s & 1)  ? 0.75f : 0.25f;
    const float yy = bh * ((float)ph + sy) - rh * 0.5f;
    const float xx = bw * ((float)pw + sx) - rw * 0.5f;
    const float x  = xx * cs + yy * sn + cx;
    const float y  = yy * cs - xx * sn + cy;

    const bool valid = (y > -1.0f) && (y < (float)FH) &&
                       (x > -1.0f) && (x < (float)FW);

    const float ycl = fminf(fmaxf(y, 0.0f), (float)(FH - 1));
    const float xcl = fminf(fmaxf(x, 0.0f), (float)(FW - 1));
    const float y0f = fminf(floorf(ycl), (float)(FH - 2));
    const float x0f = fminf(floorf(xcl), (float)(FW - 2));
    const int   y0  = (int)y0f;
    const int   x0  = (int)x0f;
    const float ly  = ycl - y0f;
    const float lx  = xcl - x0f;
    const float hy  = 1.0f - ly;
    const float hx  = 1.0f - lx;
    const float vf  = (valid && active) ? 0.25f : 0.0f;  // premult 1/(S*S)

    const int cyside = corner >> 1;       // y side of this corner
    const int cxside = corner & 1;        // x side
    float wt  = (cyside ? ly : hy) * (cxside ? lx : hx) * vf;
    int   off = (y0 + cyside) * FW + (x0 + cxside);
    if (!active) { wt = 0.0f; off = 0; }  // safe dummy address, zero weight

    const float* fb = feat + (size_t)b * CHWSZ + off;
    float*       ob = out  + (size_t)n * (CH * NBINS) + bin;
    const bool   writer = ((lane & 15) == 0) && active;

    // ---- channel mainloop: 1 LDG per lane per channel, 8 in flight ----
#pragma unroll 1
    for (int c = 0; c < CH; c += CUNROLL) {
        float v[CUNROLL];
#pragma unroll
        for (int u = 0; u < CUNROLL; ++u)
            v[u] = __ldg(fb + (size_t)(c + u) * HWSZ);
#pragma unroll
        for (int u = 0; u < CUNROLL; ++u) {
            float p = wt * v[u];
            p += __shfl_xor_sync(0xffffffffu, p, 1);
            p += __shfl_xor_sync(0xffffffffu, p, 2);
            p += __shfl_xor_sync(0xffffffffu, p, 4);
            p += __shfl_xor_sync(0xffffffffu, p, 8);
            if (writer) ob[(size_t)(c + u) * NBINS] = p;
        }
    }
}

extern "C" void kernel_launch(void* const* d_in, const int* in_sizes, int n_in,
                              void* d_out, int out_size)
{
    const float* feat = (const float*)d_in[0];
    const float* rois = (const float*)d_in[1];
    float*       out  = (float*)d_out;

    const int nrois = in_sizes[1] / 6;   // 1000

    sort_rois_kernel<<<1, 1024>>>(rois, nrois);

    dim3 grid((NBINS + BPB - 1) / BPB, nrois);   // (4, 1000)
    dim3 block(256);
    rroi_align_kernel<<<grid, block>>>(feat, rois, out);
}